// round 6
// baseline (speedup 1.0000x reference)
#include <cuda_runtime.h>
#include <math.h>
#include <stdint.h>

#define TT 4
#define VV 4096
#define EE 4096
#define KK 32
#define DD 8
#define HH 16
#define BERTD 768
#define CATD 784
#define M1 196
#define NROWS (TT * EE)
#define WSTRIDE 356   // words per kk row: >=352 for tail, ==4 mod 32, 16B-aligned

typedef unsigned long long ull;

// ---------------- scratch ----------------
__device__ __align__(256) float g_new_prices[TT * VV * HH];
__device__ __align__(256) float g_he_emb[TT * EE * HH];
__device__ __align__(256) float g_z[TT * EE];
__device__ __align__(256) float g_G[TT * EE * 64];
__device__ __align__(256) float g_gates[TT * VV * 64];
__device__ __align__(256) float g_bias[64];

__device__ __forceinline__ float sigf(float x) { return 1.0f / (1.0f + expf(-x)); }

#define FMA2(d, a, b) asm("fma.rn.f32x2 %0, %1, %2, %0;" : "+l"(d) : "l"(a), "l"(b))
#define UNPACK2(lo, hi, p) asm("mov.b64 {%0, %1}, %2;" : "=f"(lo), "=f"(hi) : "l"(p))
#define DUP2(d, v) asm("mov.b64 %0, {%1, %1};" : "=l"(d) : "f"(v))

// ============================================================================
// K0: tiny bias precompute
// ============================================================================
__global__ void k_prep_bias(const float* __restrict__ bih, const float* __restrict__ bhh) {
    int t = threadIdx.x;
    g_bias[t] = bih[t] + bhh[t];
}

// ============================================================================
// K1: price LSTM. grid 128 x block 32 (one warp per SM — latency-bound).
// ============================================================================
__global__ void k_price_lstm(const float* __restrict__ prices,
                             const float* __restrict__ Wih, const float* __restrict__ Whh,
                             const float* __restrict__ bih, const float* __restrict__ bhh) {
    __shared__ float sWih[64], sWhh[64 * 16], sb[64];
    int tid = threadIdx.x;
    for (int i = tid; i < 64; i += 32) { sWih[i] = Wih[i]; sb[i] = bih[i] + bhh[i]; }
    for (int i = tid; i < 1024; i += 32) sWhh[i] = Whh[i];
    __syncthreads();
    int v = blockIdx.x * 32 + tid;
    float h[16], c[16];
#pragma unroll
    for (int j = 0; j < 16; j++) { h[j] = 0.f; c[j] = 0.f; }
#pragma unroll
    for (int t = 0; t < TT; t++) {
        float x = prices[t * VV + v];
        float hn[16];
#pragma unroll
        for (int j = 0; j < 16; j++) {
            float gi = fmaf(sWih[j],      x, sb[j]);
            float gf = fmaf(sWih[16 + j], x, sb[16 + j]);
            float gg = fmaf(sWih[32 + j], x, sb[32 + j]);
            float go = fmaf(sWih[48 + j], x, sb[48 + j]);
#pragma unroll
            for (int u = 0; u < 16; u++) {
                float hv = h[u];
                gi = fmaf(sWhh[j * 16 + u], hv, gi);
                gf = fmaf(sWhh[(16 + j) * 16 + u], hv, gf);
                gg = fmaf(sWhh[(32 + j) * 16 + u], hv, gg);
                go = fmaf(sWhh[(48 + j) * 16 + u], hv, go);
            }
            float cn = sigf(gf) * c[j] + sigf(gi) * tanhf(gg);
            c[j] = cn;
            hn[j] = sigf(go) * tanhf(cn);
        }
#pragma unroll
        for (int j = 0; j < 16; j++) { h[j] = hn[j]; g_new_prices[(t * VV + v) * HH + j] = hn[j]; }
    }
}

// ============================================================================
// K2: VertexConv (unchanged from R5 — conflict-free transposed w2)
// ============================================================================
__global__ void __launch_bounds__(512, 1) k_vertex_conv(
        const int* __restrict__ he_members,
        const float* __restrict__ trans_w, const float* __restrict__ trans_b,
        const float* __restrict__ conv_w, const float* __restrict__ conv_b) {
    extern __shared__ char smv[];
    ull*   w2   = (ull*)smv;                         // [8][1024]
    ull*   regA = (ull*)(smv + 65536);               // [16 warps][32][9]
    float* mlt  = (float*)(smv + 102400);            // [16 warps][32][33]
    float* aA   = (float*)(smv + 169984);            // [16 warps][33]
    float* tb_s = (float*)(smv + 172096);            // [1024]
    __shared__ float s_cw[32];
    int tid = threadIdx.x;
#pragma unroll
    for (int i = 0; i < 16; i++) {
        int idx = tid + 512 * i;
        int d2 = idx >> 10, m = idx & 1023;
        float2 v = *(const float2*)(trans_w + m * 16 + d2 * 2);
        w2[d2 * 1024 + m] = *(ull*)&v;
    }
    tb_s[tid] = trans_b[tid];
    tb_s[tid + 512] = trans_b[tid + 512];
    if (tid < 32) s_cw[tid] = conv_w[tid];
    __syncthreads();
    float cb = conv_b[0];
    int w = tid >> 5, lane = tid & 31;
    int ih = blockIdx.x * 16 + w;
    int t = ih >> 12;
    ull* regw = regA + w * 288;
    float* mw = mlt + w * 1056;
    float* aw = aA + w * 33;
    {
        int vidx = he_members[ih * KK + lane];
        const float2* src = (const float2*)(g_new_prices + (t * VV + vidx) * HH);
#pragma unroll
        for (int d2 = 0; d2 < 8; d2++) {
            float2 v = src[d2];
            regw[lane * 9 + d2] = *(ull*)&v;
        }
    }
    __syncwarp();
#pragma unroll 4
    for (int k = 0; k < 32; k++) {
        const ull* rr = regw + k * 9;
        int mcol = k * 32 + lane;
        ull acc2 = 0ull;
#pragma unroll
        for (int d2 = 0; d2 < 8; d2++) FMA2(acc2, rr[d2], w2[d2 * 1024 + mcol]);
        float lo, hi;
        UNPACK2(lo, hi, acc2);
        mw[k * 33 + lane] = lo + hi + tb_s[mcol];
    }
    __syncwarp();
    {
        float r[32];
        float* mrow = mw + lane * 33;
        float mx = -1e30f;
#pragma unroll
        for (int j = 0; j < 32; j++) { r[j] = mrow[j]; mx = fmaxf(mx, r[j]); }
        float s = 0.f;
#pragma unroll
        for (int j = 0; j < 32; j++) { r[j] = expf(r[j] - mx); s += r[j]; }
        float f = s_cw[lane] / s;
#pragma unroll
        for (int j = 0; j < 32; j++) mrow[j] = r[j] * f;
    }
    __syncwarp();
    {
        float aj = 0.f;
#pragma unroll
        for (int k = 0; k < 32; k++) aj += mw[k * 33 + lane];
        aw[lane] = aj;
    }
    __syncwarp();
    if (lane < 16) {
        const float* regf = (const float*)regw;
        float acc = cb;
#pragma unroll
        for (int j = 0; j < 32; j++) acc = fmaf(aw[j], regf[j * 18 + lane], acc);
        g_he_emb[ih * HH + lane] = acc;
    }
}

// ============================================================================
// K3 v4: FFMA2 GEMM, double-buffered shared, ONE sync per K-chunk.
// wd row stride 356 words (race-free tail region; 2-way max store conflicts).
// Shared layout (bytes):
//   wd0 @0 (22784) | wd1 @22784 | a0 @45568 (8448) | a1 @54016 |
//   sb1 @62464 | sw2 @63248 | zred @64032 (8704) -> 72736 total
// ============================================================================
__global__ void __launch_bounds__(512, 1) k_he_gemm(
        const float* __restrict__ node_embs,
        const float* __restrict__ W1, const float* __restrict__ Wm,
        const float* __restrict__ b1, const float* __restrict__ w2,
        const float* __restrict__ b2v) {
    extern __shared__ char smg[];
    float* wd0  = (float*)smg;
    float* wd1  = (float*)(smg + 22784);
    float* a0   = (float*)(smg + 45568);
    float* a1   = (float*)(smg + 54016);
    float* sb1  = (float*)(smg + 62464);
    float* sw2  = (float*)(smg + 63248);
    float* zred = (float*)(smg + 64032);

    int tid = threadIdx.x;
    int cg = tid & 15, rg = tid >> 4;
    int row0 = blockIdx.x * 128;

    if (tid < M1) { sb1[tid] = b1[tid]; sw2[tid] = w2[tid]; }

    // staging slots: modes 0 skip, 1 main, 2 tail-real, 3 tail-zero
    uint32_t wsts[9]; const float* wsrc[9]; int wmode[9];
#pragma unroll
    for (int i = 0; i < 9; i++) {
        int idx = tid + 512 * i;
        int kk = idx & 15, m = idx >> 4;
        if (m >= 272) { wmode[i] = 0; wsts[i] = 0; wsrc[i] = W1; }
        else if (m < 256) {
            wmode[i] = 1;
            wsts[i] = (uint32_t)(kk * WSTRIDE + (m >> 4) * 20 + (m & 15));
            wsrc[i] = (m < M1 ? W1 + m * CATD : Wm + (m - M1) * CATD) + kk;
        } else {
            wsts[i] = (uint32_t)(kk * WSTRIDE + 320 + 2 * (m - 256));
            if (m < 260) { wmode[i] = 2; wsrc[i] = Wm + (m - M1) * CATD + kk; }
            else         { wmode[i] = 3; wsrc[i] = W1; }
        }
    }
    uint32_t asts[4]; const float* asrc[4];
#pragma unroll
    for (int i = 0; i < 4; i++) {
        int idx = tid + 512 * i;
        int kk = idx & 15, r = idx >> 4;
        asts[i] = (uint32_t)(kk * 132 + r);
        asrc[i] = node_embs + (size_t)(row0 + r) * BERTD + kk;  // chunk>=1 source
    }

    // prefetch chunk 0
    float wpre[9], apre[4];
#pragma unroll
    for (int i = 0; i < 9; i++) wpre[i] = (wmode[i] == 1 || wmode[i] == 2) ? *wsrc[i] : 0.f;
#pragma unroll
    for (int i = 0; i < 4; i++) {
        int idx = tid + 512 * i;
        int kk = idx & 15, r = idx >> 4;
        apre[i] = g_he_emb[(row0 + r) * HH + kk];
    }

    ull acc[4][8], acct[4];
#pragma unroll
    for (int r = 0; r < 4; r++) {
        acct[r] = 0ull;
#pragma unroll
        for (int p = 0; p < 8; p++) acc[r][p] = 0ull;
    }

    for (int ch = 0; ch < 49; ch++) {
        int b = ch & 1;
        float* wdb = b ? wd1 : wd0;
        float* asb = b ? a1 : a0;
        // commit staged regs for THIS chunk into buffer b
#pragma unroll
        for (int i = 0; i < 9; i++) {
            if (wmode[i] == 1) wdb[wsts[i]] = wpre[i];
            else if (wmode[i] >= 2) {
                ull dv; DUP2(dv, wpre[i]);
                *(ull*)(wdb + wsts[i]) = dv;
            }
        }
#pragma unroll
        for (int i = 0; i < 4; i++) asb[asts[i]] = apre[i];
        __syncthreads();
        // prefetch next chunk into regs (overlaps compute)
        if (ch < 48) {
#pragma unroll
            for (int i = 0; i < 9; i++) {
                if (wmode[i] == 1 || wmode[i] == 2) { wpre[i] = wsrc[i][16]; wsrc[i] += 16; }
            }
#pragma unroll
            for (int i = 0; i < 4; i++) { apre[i] = asrc[i][0]; asrc[i] += 16; }
        }
        // compute this chunk from buffer b
#pragma unroll 4
        for (int kk = 0; kk < 16; kk++) {
            float4 av = *(const float4*)(asb + kk * 132 + rg * 4);
            ull ad0, ad1, ad2, ad3;
            DUP2(ad0, av.x); DUP2(ad1, av.y); DUP2(ad2, av.z); DUP2(ad3, av.w);
            const float* wrow = wdb + kk * WSTRIDE + cg * 20;
            ulonglong2 w01 = *(const ulonglong2*)(wrow);
            ulonglong2 w23 = *(const ulonglong2*)(wrow + 4);
            ulonglong2 w45 = *(const ulonglong2*)(wrow + 8);
            ulonglong2 w67 = *(const ulonglong2*)(wrow + 12);
            FMA2(acc[0][0], ad0, w01.x); FMA2(acc[1][0], ad1, w01.x);
            FMA2(acc[2][0], ad2, w01.x); FMA2(acc[3][0], ad3, w01.x);
            FMA2(acc[0][1], ad0, w01.y); FMA2(acc[1][1], ad1, w01.y);
            FMA2(acc[2][1], ad2, w01.y); FMA2(acc[3][1], ad3, w01.y);
            FMA2(acc[0][2], ad0, w23.x); FMA2(acc[1][2], ad1, w23.x);
            FMA2(acc[2][2], ad2, w23.x); FMA2(acc[3][2], ad3, w23.x);
            FMA2(acc[0][3], ad0, w23.y); FMA2(acc[1][3], ad1, w23.y);
            FMA2(acc[2][3], ad2, w23.y); FMA2(acc[3][3], ad3, w23.y);
            FMA2(acc[0][4], ad0, w45.x); FMA2(acc[1][4], ad1, w45.x);
            FMA2(acc[2][4], ad2, w45.x); FMA2(acc[3][4], ad3, w45.x);
            FMA2(acc[0][5], ad0, w45.y); FMA2(acc[1][5], ad1, w45.y);
            FMA2(acc[2][5], ad2, w45.y); FMA2(acc[3][5], ad3, w45.y);
            FMA2(acc[0][6], ad0, w67.x); FMA2(acc[1][6], ad1, w67.x);
            FMA2(acc[2][6], ad2, w67.x); FMA2(acc[3][6], ad3, w67.x);
            FMA2(acc[0][7], ad0, w67.y); FMA2(acc[1][7], ad1, w67.y);
            FMA2(acc[2][7], ad2, w67.y); FMA2(acc[3][7], ad3, w67.y);
            ull wt = *(const ull*)(wdb + kk * WSTRIDE + 320 + 2 * cg);
            FMA2(acct[0], ad0, wt); FMA2(acct[1], ad1, wt);
            FMA2(acct[2], ad2, wt); FMA2(acct[3], ad3, wt);
        }
    }

    // epilogue
    int ct = 256 + cg;
#pragma unroll
    for (int r = 0; r < 4; r++) {
        int row = row0 + rg * 4 + r;
        float zp = 0.f;
#pragma unroll
        for (int p = 0; p < 8; p++) {
            int c = cg * 16 + 2 * p;
            float lo, hi;
            UNPACK2(lo, hi, acc[r][p]);
            if (c < M1) {
                zp = fmaf(sw2[c],     fmaxf(lo + sb1[c], 0.f),     zp);
                zp = fmaf(sw2[c + 1], fmaxf(hi + sb1[c + 1], 0.f), zp);
            } else if (c < 260) {
                float2 gv = make_float2(lo, hi);
                *(float2*)(g_G + (size_t)row * 64 + (c - M1)) = gv;
            }
        }
        if (ct < 260) {
            float lo, hi;
            UNPACK2(lo, hi, acct[r]);
            g_G[(size_t)row * 64 + (ct - M1)] = lo;
        }
        zred[(rg * 4 + r) * 17 + cg] = zp;
    }
    __syncthreads();
    if (tid < 128) {
        float s = b2v[0];
#pragma unroll
        for (int c = 0; c < 16; c++) s += zred[tid * 17 + c];
        g_z[row0 + tid] = s;
    }
}

// ============================================================================
// K4: per-vertex softmax over 8 edges + weighted sum of G rows -> gates.
// ============================================================================
__global__ void __launch_bounds__(256) k_gather_gates(const int* __restrict__ ve) {
    __shared__ float sbias[64];
    int tid = threadIdx.x;
    if (tid < 64) sbias[tid] = g_bias[tid];
    __syncthreads();
    int w = tid >> 5, lane = tid & 31;
    int tv = blockIdx.x * 8 + w;
    int t = tv >> 12;
    int eld = 0;
    if (lane < 8) eld = ve[tv * DD + lane];
    float zld = (lane < 8) ? g_z[t * EE + eld] : 0.f;
    float zv[8]; int ev[8];
#pragma unroll
    for (int d = 0; d < 8; d++) {
        zv[d] = __shfl_sync(0xffffffffu, zld, d);
        ev[d] = __shfl_sync(0xffffffffu, eld, d);
    }
    float mx = zv[0];
#pragma unroll
    for (int d = 1; d < 8; d++) mx = fmaxf(mx, zv[d]);
    float s = 0.f;
#pragma unroll
    for (int d = 0; d < 8; d++) { zv[d] = expf(zv[d] - mx); s += zv[d]; }
    float inv = 1.f / s;
    float a0 = 0.f, a1 = 0.f;
#pragma unroll
    for (int d = 0; d < 8; d++) {
        const float* gr = g_G + (size_t)(t * EE + ev[d]) * 64;
        float wv = zv[d] * inv;
        a0 = fmaf(wv, gr[lane], a0);
        a1 = fmaf(wv, gr[lane + 32], a1);
    }
    g_gates[(size_t)tv * 64 + lane]      = a0 + sbias[lane];
    g_gates[(size_t)tv * 64 + lane + 32] = a1 + sbias[lane + 32];
}

// ============================================================================
// K5: second LSTM + residual + attention + FC. grid 128 x block 32.
// ============================================================================
__global__ void k_final(const float* __restrict__ Whh,
                        const float* __restrict__ attn_in, const float* __restrict__ attn_out,
                        const float* __restrict__ fc_w, const float* __restrict__ fc_b,
                        float* __restrict__ out) {
    __shared__ float sWhh[1024], sAin[256], sAout[512], sFc[32], sFcb[2];
    int tid = threadIdx.x;
    for (int i = tid; i < 1024; i += 32) sWhh[i] = Whh[i];
    for (int i = tid; i < 256; i += 32) sAin[i] = attn_in[i];
    for (int i = tid; i < 512; i += 32) sAout[i] = attn_out[i];
    if (tid < 32) sFc[tid] = fc_w[tid];
    if (tid < 2) sFcb[tid] = fc_b[tid];
    __syncthreads();
    int v = blockIdx.x * 32 + tid;
    float h[16], c[16], la[4][16];
#pragma unroll
    for (int j = 0; j < 16; j++) { h[j] = 0.f; c[j] = 0.f; }
#pragma unroll
    for (int t = 0; t < 4; t++) {
        float gin[64];
        const float4* gp = (const float4*)(g_gates + (size_t)(t * VV + v) * 64);
#pragma unroll
        for (int i = 0; i < 16; i++) {
            float4 x = gp[i];
            gin[4 * i] = x.x; gin[4 * i + 1] = x.y; gin[4 * i + 2] = x.z; gin[4 * i + 3] = x.w;
        }
        float hn[16];
#pragma unroll
        for (int j = 0; j < 16; j++) {
            float gi = gin[j], gf = gin[16 + j], gg = gin[32 + j], go = gin[48 + j];
#pragma unroll
            for (int u = 0; u < 16; u++) {
                float hv = h[u];
                gi = fmaf(sWhh[j * 16 + u], hv, gi);
                gf = fmaf(sWhh[(16 + j) * 16 + u], hv, gf);
                gg = fmaf(sWhh[(32 + j) * 16 + u], hv, gg);
                go = fmaf(sWhh[(48 + j) * 16 + u], hv, go);
            }
            float cn = sigf(gf) * c[j] + sigf(gi) * tanhf(gg);
            c[j] = cn;
            hn[j] = sigf(go) * tanhf(cn);
        }
#pragma unroll
        for (int j = 0; j < 16; j++) {
            h[j] = hn[j];
            la[t][j] = hn[j] + g_new_prices[(t * VV + v) * HH + j];
        }
    }
    float q[16];
#pragma unroll
    for (int j = 0; j < 16; j++) {
        float a = 0.f;
#pragma unroll
        for (int u = 0; u < 16; u++) a = fmaf(sAin[j * 16 + u], la[3][u], a);
        q[j] = a;
    }
    float sc[4], mx = -1e30f;
#pragma unroll
    for (int t = 0; t < 4; t++) {
        float a = 0.f;
#pragma unroll
        for (int j = 0; j < 16; j++) a = fmaf(q[j], la[t][j], a);
        sc[t] = a;
        mx = fmaxf(mx, a);
    }
    float ssum = 0.f;
#pragma unroll
    for (int t = 0; t < 4; t++) { sc[t] = expf(sc[t] - mx); ssum += sc[t]; }
    float inv = 1.f / ssum;
    float mixv[16];
#pragma unroll
    for (int j = 0; j < 16; j++) {
        float m = 0.f;
#pragma unroll
        for (int t = 0; t < 4; t++) m = fmaf(sc[t] * inv, la[t][j], m);
        mixv[j] = m;
    }
    float attn[16];
#pragma unroll
    for (int j = 0; j < 16; j++) {
        float a = 0.f;
#pragma unroll
        for (int u = 0; u < 16; u++) a = fmaf(sAout[j * 32 + u], mixv[u], a);
#pragma unroll
        for (int u = 0; u < 16; u++) a = fmaf(sAout[j * 32 + 16 + u], q[u], a);
        attn[j] = tanhf(a);
    }
#pragma unroll
    for (int o = 0; o < 2; o++) {
        float a = sFcb[o];
#pragma unroll
        for (int j = 0; j < 16; j++) a = fmaf(sFc[o * 16 + j], attn[j], a);
        out[v * 2 + o] = a;
    }
}

// ============================================================================
extern "C" void kernel_launch(void* const* d_in, const int* in_sizes, int n_in,
                              void* d_out, int out_size) {
    const float* prices = (const float*)d_in[0];
    const float* node   = (const float*)d_in[1];
    const int*   he_mem = (const int*)d_in[2];
    const int*   ve     = (const int*)d_in[3];
    const float* Wih_p  = (const float*)d_in[4];
    const float* Whh_p  = (const float*)d_in[5];
    const float* bih_p  = (const float*)d_in[6];
    const float* bhh_p  = (const float*)d_in[7];
    const float* Wih_m  = (const float*)d_in[8];
    const float* Whh_m  = (const float*)d_in[9];
    const float* bih_m  = (const float*)d_in[10];
    const float* bhh_m  = (const float*)d_in[11];
    const float* tw     = (const float*)d_in[12];
    const float* tb     = (const float*)d_in[13];
    const float* cw     = (const float*)d_in[14];
    const float* cbv    = (const float*)d_in[15];
    const float* w1     = (const float*)d_in[16];
    const float* b1     = (const float*)d_in[17];
    const float* w2     = (const float*)d_in[18];
    const float* b2     = (const float*)d_in[19];
    const float* ain    = (const float*)d_in[20];
    const float* aout   = (const float*)d_in[21];
    const float* fcw    = (const float*)d_in[22];
    const float* fcb    = (const float*)d_in[23];
    float* out = (float*)d_out;
    (void)in_sizes; (void)n_in; (void)out_size;

    const int smem_vc = 176192;
    const int smem_ge = 72736;
    cudaFuncSetAttribute(k_vertex_conv, cudaFuncAttributeMaxDynamicSharedMemorySize, smem_vc);
    cudaFuncSetAttribute(k_he_gemm, cudaFuncAttributeMaxDynamicSharedMemorySize, smem_ge);

    k_prep_bias<<<1, 64>>>(bih_m, bhh_m);
    k_price_lstm<<<128, 32>>>(prices, Wih_p, Whh_p, bih_p, bhh_p);
    k_vertex_conv<<<TT * EE / 16, 512, smem_vc>>>(he_mem, tw, tb, cw, cbv);
    k_he_gemm<<<NROWS / 128, 512, smem_ge>>>(node, w1, Wih_m, b1, w2, b2);
    k_gather_gates<<<TT * VV / 8, 256>>>(ve);
    k_final<<<128, 32>>>(Whh_m, ain, aout, fcw, fcb, out);
}

// round 7
// speedup vs baseline: 1.1251x; 1.1251x over previous
#include <cuda_runtime.h>
#include <math.h>
#include <stdint.h>

#define TT 4
#define VV 4096
#define EE 4096
#define KK 32
#define DD 8
#define HH 16
#define BERTD 768
#define CATD 784
#define M1 196
#define NROWS (TT * EE)
#define WSTRIDE 356   // words per kk row: >=352 for tail (race-free), ==4 mod 32, 16B-aligned

typedef unsigned long long ull;

// ---------------- scratch ----------------
__device__ __align__(256) float g_new_prices[TT * VV * HH];
__device__ __align__(256) float g_he_emb[TT * EE * HH];
__device__ __align__(256) float g_z[TT * EE];
__device__ __align__(256) float g_G[TT * EE * 64];
__device__ __align__(256) float g_gates[TT * VV * 64];
__device__ __align__(256) float g_bias[64];

__device__ __forceinline__ float sigf(float x) { return 1.0f / (1.0f + __expf(-x)); }

#define FMA2(d, a, b) asm("fma.rn.f32x2 %0, %1, %2, %0;" : "+l"(d) : "l"(a), "l"(b))
#define UNPACK2(lo, hi, p) asm("mov.b64 {%0, %1}, %2;" : "=f"(lo), "=f"(hi) : "l"(p))
#define DUP2(d, v) asm("mov.b64 %0, {%1, %1};" : "=l"(d) : "f"(v))

// ============================================================================
// K0: tiny bias precompute
// ============================================================================
__global__ void k_prep_bias(const float* __restrict__ bih, const float* __restrict__ bhh) {
    int t = threadIdx.x;
    g_bias[t] = bih[t] + bhh[t];
}

// ============================================================================
// K1: price LSTM. 32 blocks x 128 threads (reverted — best measured config).
// ============================================================================
__global__ void k_price_lstm(const float* __restrict__ prices,
                             const float* __restrict__ Wih, const float* __restrict__ Whh,
                             const float* __restrict__ bih, const float* __restrict__ bhh) {
    __shared__ float sWih[64], sWhh[64 * 16], sb[64];
    int tid = threadIdx.x;
    for (int i = tid; i < 64; i += 128) { sWih[i] = Wih[i]; sb[i] = bih[i] + bhh[i]; }
    for (int i = tid; i < 1024; i += 128) sWhh[i] = Whh[i];
    __syncthreads();
    int v = blockIdx.x * 128 + tid;
    float h[16], c[16];
#pragma unroll
    for (int j = 0; j < 16; j++) { h[j] = 0.f; c[j] = 0.f; }
#pragma unroll
    for (int t = 0; t < TT; t++) {
        float x = prices[t * VV + v];
        float hn[16];
#pragma unroll
        for (int j = 0; j < 16; j++) {
            float gi = fmaf(sWih[j],      x, sb[j]);
            float gf = fmaf(sWih[16 + j], x, sb[16 + j]);
            float gg = fmaf(sWih[32 + j], x, sb[32 + j]);
            float go = fmaf(sWih[48 + j], x, sb[48 + j]);
#pragma unroll
            for (int u = 0; u < 16; u++) {
                float hv = h[u];
                gi = fmaf(sWhh[j * 16 + u], hv, gi);
                gf = fmaf(sWhh[(16 + j) * 16 + u], hv, gf);
                gg = fmaf(sWhh[(32 + j) * 16 + u], hv, gg);
                go = fmaf(sWhh[(48 + j) * 16 + u], hv, go);
            }
            float cn = sigf(gf) * c[j] + sigf(gi) * tanhf(gg);
            c[j] = cn;
            hn[j] = sigf(go) * tanhf(cn);
        }
#pragma unroll
        for (int j = 0; j < 16; j++) { h[j] = hn[j]; g_new_prices[(t * VV + v) * HH + j] = hn[j]; }
    }
}

// ============================================================================
// K2: VertexConv — __expf softmax (the hidden 200us was accurate expf).
// ============================================================================
__global__ void __launch_bounds__(512, 1) k_vertex_conv(
        const int* __restrict__ he_members,
        const float* __restrict__ trans_w, const float* __restrict__ trans_b,
        const float* __restrict__ conv_w, const float* __restrict__ conv_b) {
    extern __shared__ char smv[];
    ull*   w2   = (ull*)smv;                         // [8][1024]
    ull*   regA = (ull*)(smv + 65536);               // [16 warps][32][9]
    float* mlt  = (float*)(smv + 102400);            // [16 warps][32][33]
    float* aA   = (float*)(smv + 169984);            // [16 warps][33]
    float* tb_s = (float*)(smv + 172096);            // [1024]
    __shared__ float s_cw[32];
    int tid = threadIdx.x;
#pragma unroll
    for (int i = 0; i < 16; i++) {
        int idx = tid + 512 * i;
        int d2 = idx >> 10, m = idx & 1023;
        float2 v = *(const float2*)(trans_w + m * 16 + d2 * 2);
        w2[d2 * 1024 + m] = *(ull*)&v;
    }
    tb_s[tid] = trans_b[tid];
    tb_s[tid + 512] = trans_b[tid + 512];
    if (tid < 32) s_cw[tid] = conv_w[tid];
    __syncthreads();
    float cb = conv_b[0];
    int w = tid >> 5, lane = tid & 31;
    int ih = blockIdx.x * 16 + w;
    int t = ih >> 12;
    ull* regw = regA + w * 288;
    float* mw = mlt + w * 1056;
    float* aw = aA + w * 33;
    {
        int vidx = he_members[ih * KK + lane];
        const float2* src = (const float2*)(g_new_prices + (t * VV + vidx) * HH);
#pragma unroll
        for (int d2 = 0; d2 < 8; d2++) {
            float2 v = src[d2];
            regw[lane * 9 + d2] = *(ull*)&v;
        }
    }
    __syncwarp();
#pragma unroll 4
    for (int k = 0; k < 32; k++) {
        const ull* rr = regw + k * 9;
        int mcol = k * 32 + lane;
        ull acc2 = 0ull;
#pragma unroll
        for (int d2 = 0; d2 < 8; d2++) FMA2(acc2, rr[d2], w2[d2 * 1024 + mcol]);
        float lo, hi;
        UNPACK2(lo, hi, acc2);
        mw[k * 33 + lane] = lo + hi + tb_s[mcol];
    }
    __syncwarp();
    {   // softmax over j for row k=lane; fast exp; write back e * cw[k]/S
        float r[32];
        float* mrow = mw + lane * 33;
        float mx = -1e30f;
#pragma unroll
        for (int j = 0; j < 32; j++) { r[j] = mrow[j]; mx = fmaxf(mx, r[j]); }
        float s = 0.f;
#pragma unroll
        for (int j = 0; j < 32; j++) { r[j] = __expf(r[j] - mx); s += r[j]; }
        float f = s_cw[lane] / s;
#pragma unroll
        for (int j = 0; j < 32; j++) mrow[j] = r[j] * f;
    }
    __syncwarp();
    {
        float aj = 0.f;
#pragma unroll
        for (int k = 0; k < 32; k++) aj += mw[k * 33 + lane];
        aw[lane] = aj;
    }
    __syncwarp();
    if (lane < 16) {
        const float* regf = (const float*)regw;
        float acc = cb;
#pragma unroll
        for (int j = 0; j < 32; j++) acc = fmaf(aw[j], regf[j * 18 + lane], acc);
        g_he_emb[ih * HH + lane] = acc;
    }
}

// ============================================================================
// K3: FFMA2 GEMM — R5 structure (single buffer, 2 syncs/chunk; best measured)
// with the race-free WSTRIDE=356 layout.
// Shared: wd 22784 | a_s @22784 (8448) | sb1 @31232 | sw2 @32016 |
//   zred @32800 (8704) -> 41504 total
// ============================================================================
__global__ void __launch_bounds__(512, 1) k_he_gemm(
        const float* __restrict__ node_embs,
        const float* __restrict__ W1, const float* __restrict__ Wm,
        const float* __restrict__ b1, const float* __restrict__ w2,
        const float* __restrict__ b2v) {
    extern __shared__ char smg[];
    float* wd   = (float*)smg;               // [16][356]
    float* a_s  = (float*)(smg + 22784);     // [16][132]
    float* sb1  = (float*)(smg + 31232);     // [196]
    float* sw2  = (float*)(smg + 32016);     // [196]
    float* zred = (float*)(smg + 32800);     // [128][17]

    int tid = threadIdx.x;
    int cg = tid & 15, rg = tid >> 4;
    int row0 = blockIdx.x * 128;

    if (tid < M1) { sb1[tid] = b1[tid]; sw2[tid] = w2[tid]; }

    // staging slots: modes 0 skip, 1 main, 2 tail-real, 3 tail-zero
    uint32_t wsts[9]; const float* wsrc[9]; int wmode[9];
#pragma unroll
    for (int i = 0; i < 9; i++) {
        int idx = tid + 512 * i;
        int kk = idx & 15, m = idx >> 4;
        if (m >= 272) { wmode[i] = 0; wsts[i] = 0; wsrc[i] = W1; }
        else if (m < 256) {
            wmode[i] = 1;
            wsts[i] = (uint32_t)(kk * WSTRIDE + (m >> 4) * 20 + (m & 15));
            wsrc[i] = (m < M1 ? W1 + m * CATD : Wm + (m - M1) * CATD) + kk;
        } else {
            wsts[i] = (uint32_t)(kk * WSTRIDE + 320 + 2 * (m - 256));
            if (m < 260) { wmode[i] = 2; wsrc[i] = Wm + (m - M1) * CATD + kk; }
            else         { wmode[i] = 3; wsrc[i] = W1; }
        }
    }
    uint32_t asts[4]; const float* asrc[4];
#pragma unroll
    for (int i = 0; i < 4; i++) {
        int idx = tid + 512 * i;
        int kk = idx & 15, r = idx >> 4;
        asts[i] = (uint32_t)(kk * 132 + r);
        asrc[i] = node_embs + (size_t)(row0 + r) * BERTD + kk;  // chunk>=1 source
    }

    // prefetch chunk 0
    float wpre[9], apre[4];
#pragma unroll
    for (int i = 0; i < 9; i++) wpre[i] = (wmode[i] == 1 || wmode[i] == 2) ? *wsrc[i] : 0.f;
#pragma unroll
    for (int i = 0; i < 4; i++) {
        int idx = tid + 512 * i;
        int kk = idx & 15, r = idx >> 4;
        apre[i] = g_he_emb[(row0 + r) * HH + kk];
    }

    ull acc[4][8], acct[4];
#pragma unroll
    for (int r = 0; r < 4; r++) {
        acct[r] = 0ull;
#pragma unroll
        for (int p = 0; p < 8; p++) acc[r][p] = 0ull;
    }

    for (int ch = 0; ch < 49; ch++) {
        // commit staged regs
#pragma unroll
        for (int i = 0; i < 9; i++) {
            if (wmode[i] == 1) wd[wsts[i]] = wpre[i];
            else if (wmode[i] >= 2) {
                ull dv; DUP2(dv, wpre[i]);
                *(ull*)(wd + wsts[i]) = dv;
            }
        }
#pragma unroll
        for (int i = 0; i < 4; i++) a_s[asts[i]] = apre[i];
        __syncthreads();
        // prefetch next chunk (overlaps compute)
        if (ch < 48) {
#pragma unroll
            for (int i = 0; i < 9; i++) {
                if (wmode[i] == 1 || wmode[i] == 2) { wpre[i] = wsrc[i][16]; wsrc[i] += 16; }
            }
#pragma unroll
            for (int i = 0; i < 4; i++) { apre[i] = asrc[i][0]; asrc[i] += 16; }
        }
        // compute chunk
#pragma unroll 4
        for (int kk = 0; kk < 16; kk++) {
            float4 av = *(const float4*)(a_s + kk * 132 + rg * 4);
            ull ad0, ad1, ad2, ad3;
            DUP2(ad0, av.x); DUP2(ad1, av.y); DUP2(ad2, av.z); DUP2(ad3, av.w);
            const float* wrow = wd + kk * WSTRIDE + cg * 20;
            ulonglong2 w01 = *(const ulonglong2*)(wrow);
            ulonglong2 w23 = *(const ulonglong2*)(wrow + 4);
            ulonglong2 w45 = *(const ulonglong2*)(wrow + 8);
            ulonglong2 w67 = *(const ulonglong2*)(wrow + 12);
            FMA2(acc[0][0], ad0, w01.x); FMA2(acc[1][0], ad1, w01.x);
            FMA2(acc[2][0], ad2, w01.x); FMA2(acc[3][0], ad3, w01.x);
            FMA2(acc[0][1], ad0, w01.y); FMA2(acc[1][1], ad1, w01.y);
            FMA2(acc[2][1], ad2, w01.y); FMA2(acc[3][1], ad3, w01.y);
            FMA2(acc[0][2], ad0, w23.x); FMA2(acc[1][2], ad1, w23.x);
            FMA2(acc[2][2], ad2, w23.x); FMA2(acc[3][2], ad3, w23.x);
            FMA2(acc[0][3], ad0, w23.y); FMA2(acc[1][3], ad1, w23.y);
            FMA2(acc[2][3], ad2, w23.y); FMA2(acc[3][3], ad3, w23.y);
            FMA2(acc[0][4], ad0, w45.x); FMA2(acc[1][4], ad1, w45.x);
            FMA2(acc[2][4], ad2, w45.x); FMA2(acc[3][4], ad3, w45.x);
            FMA2(acc[0][5], ad0, w45.y); FMA2(acc[1][5], ad1, w45.y);
            FMA2(acc[2][5], ad2, w45.y); FMA2(acc[3][5], ad3, w45.y);
            FMA2(acc[0][6], ad0, w67.x); FMA2(acc[1][6], ad1, w67.x);
            FMA2(acc[2][6], ad2, w67.x); FMA2(acc[3][6], ad3, w67.x);
            FMA2(acc[0][7], ad0, w67.y); FMA2(acc[1][7], ad1, w67.y);
            FMA2(acc[2][7], ad2, w67.y); FMA2(acc[3][7], ad3, w67.y);
            ull wt = *(const ull*)(wd + kk * WSTRIDE + 320 + 2 * cg);
            FMA2(acct[0], ad0, wt); FMA2(acct[1], ad1, wt);
            FMA2(acct[2], ad2, wt); FMA2(acct[3], ad3, wt);
        }
        __syncthreads();
    }

    // epilogue
    int ct = 256 + cg;
#pragma unroll
    for (int r = 0; r < 4; r++) {
        int row = row0 + rg * 4 + r;
        float zp = 0.f;
#pragma unroll
        for (int p = 0; p < 8; p++) {
            int c = cg * 16 + 2 * p;
            float lo, hi;
            UNPACK2(lo, hi, acc[r][p]);
            if (c < M1) {
                zp = fmaf(sw2[c],     fmaxf(lo + sb1[c], 0.f),     zp);
                zp = fmaf(sw2[c + 1], fmaxf(hi + sb1[c + 1], 0.f), zp);
            } else if (c < 260) {
                float2 gv = make_float2(lo, hi);
                *(float2*)(g_G + (size_t)row * 64 + (c - M1)) = gv;
            }
        }
        if (ct < 260) {
            float lo, hi;
            UNPACK2(lo, hi, acct[r]);
            g_G[(size_t)row * 64 + (ct - M1)] = lo;
        }
        zred[(rg * 4 + r) * 17 + cg] = zp;
    }
    __syncthreads();
    if (tid < 128) {
        float s = b2v[0];
#pragma unroll
        for (int c = 0; c < 16; c++) s += zred[tid * 17 + c];
        g_z[row0 + tid] = s;
    }
}

// ============================================================================
// K4: per-vertex softmax over 8 edges + weighted sum of G rows -> gates.
// ============================================================================
__global__ void __launch_bounds__(256) k_gather_gates(const int* __restrict__ ve) {
    __shared__ float sbias[64];
    int tid = threadIdx.x;
    if (tid < 64) sbias[tid] = g_bias[tid];
    __syncthreads();
    int w = tid >> 5, lane = tid & 31;
    int tv = blockIdx.x * 8 + w;
    int t = tv >> 12;
    int eld = 0;
    if (lane < 8) eld = ve[tv * DD + lane];
    float zld = (lane < 8) ? g_z[t * EE + eld] : 0.f;
    float zv[8]; int ev[8];
#pragma unroll
    for (int d = 0; d < 8; d++) {
        zv[d] = __shfl_sync(0xffffffffu, zld, d);
        ev[d] = __shfl_sync(0xffffffffu, eld, d);
    }
    float mx = zv[0];
#pragma unroll
    for (int d = 1; d < 8; d++) mx = fmaxf(mx, zv[d]);
    float s = 0.f;
#pragma unroll
    for (int d = 0; d < 8; d++) { zv[d] = __expf(zv[d] - mx); s += zv[d]; }
    float inv = 1.f / s;
    float a0 = 0.f, a1 = 0.f;
#pragma unroll
    for (int d = 0; d < 8; d++) {
        const float* gr = g_G + (size_t)(t * EE + ev[d]) * 64;
        float wv = zv[d] * inv;
        a0 = fmaf(wv, gr[lane], a0);
        a1 = fmaf(wv, gr[lane + 32], a1);
    }
    g_gates[(size_t)tv * 64 + lane]      = a0 + sbias[lane];
    g_gates[(size_t)tv * 64 + lane + 32] = a1 + sbias[lane + 32];
}

// ============================================================================
// K5: second LSTM + residual + attention + FC. 32 blocks x 128 threads.
// ============================================================================
__global__ void k_final(const float* __restrict__ Whh,
                        const float* __restrict__ attn_in, const float* __restrict__ attn_out,
                        const float* __restrict__ fc_w, const float* __restrict__ fc_b,
                        float* __restrict__ out) {
    __shared__ float sWhh[1024], sAin[256], sAout[512], sFc[32], sFcb[2];
    int tid = threadIdx.x;
    for (int i = tid; i < 1024; i += 128) sWhh[i] = Whh[i];
    for (int i = tid; i < 256; i += 128) sAin[i] = attn_in[i];
    for (int i = tid; i < 512; i += 128) sAout[i] = attn_out[i];
    if (tid < 32) sFc[tid] = fc_w[tid];
    if (tid < 2) sFcb[tid] = fc_b[tid];
    __syncthreads();
    int v = blockIdx.x * 128 + tid;
    float h[16], c[16], la[4][16];
#pragma unroll
    for (int j = 0; j < 16; j++) { h[j] = 0.f; c[j] = 0.f; }
#pragma unroll
    for (int t = 0; t < 4; t++) {
        float gin[64];
        const float4* gp = (const float4*)(g_gates + (size_t)(t * VV + v) * 64);
#pragma unroll
        for (int i = 0; i < 16; i++) {
            float4 x = gp[i];
            gin[4 * i] = x.x; gin[4 * i + 1] = x.y; gin[4 * i + 2] = x.z; gin[4 * i + 3] = x.w;
        }
        float hn[16];
#pragma unroll
        for (int j = 0; j < 16; j++) {
            float gi = gin[j], gf = gin[16 + j], gg = gin[32 + j], go = gin[48 + j];
#pragma unroll
            for (int u = 0; u < 16; u++) {
                float hv = h[u];
                gi = fmaf(sWhh[j * 16 + u], hv, gi);
                gf = fmaf(sWhh[(16 + j) * 16 + u], hv, gf);
                gg = fmaf(sWhh[(32 + j) * 16 + u], hv, gg);
                go = fmaf(sWhh[(48 + j) * 16 + u], hv, go);
            }
            float cn = sigf(gf) * c[j] + sigf(gi) * tanhf(gg);
            c[j] = cn;
            hn[j] = sigf(go) * tanhf(cn);
        }
#pragma unroll
        for (int j = 0; j < 16; j++) {
            h[j] = hn[j];
            la[t][j] = hn[j] + g_new_prices[(t * VV + v) * HH + j];
        }
    }
    float q[16];
#pragma unroll
    for (int j = 0; j < 16; j++) {
        float a = 0.f;
#pragma unroll
        for (int u = 0; u < 16; u++) a = fmaf(sAin[j * 16 + u], la[3][u], a);
        q[j] = a;
    }
    float sc[4], mx = -1e30f;
#pragma unroll
    for (int t = 0; t < 4; t++) {
        float a = 0.f;
#pragma unroll
        for (int j = 0; j < 16; j++) a = fmaf(q[j], la[t][j], a);
        sc[t] = a;
        mx = fmaxf(mx, a);
    }
    float ssum = 0.f;
#pragma unroll
    for (int t = 0; t < 4; t++) { sc[t] = __expf(sc[t] - mx); ssum += sc[t]; }
    float inv = 1.f / ssum;
    float mixv[16];
#pragma unroll
    for (int j = 0; j < 16; j++) {
        float m = 0.f;
#pragma unroll
        for (int t = 0; t < 4; t++) m = fmaf(sc[t] * inv, la[t][j], m);
        mixv[j] = m;
    }
    float attn[16];
#pragma unroll
    for (int j = 0; j < 16; j++) {
        float a = 0.f;
#pragma unroll
        for (int u = 0; u < 16; u++) a = fmaf(sAout[j * 32 + u], mixv[u], a);
#pragma unroll
        for (int u = 0; u < 16; u++) a = fmaf(sAout[j * 32 + 16 + u], q[u], a);
        attn[j] = tanhf(a);
    }
#pragma unroll
    for (int o = 0; o < 2; o++) {
        float a = sFcb[o];
#pragma unroll
        for (int j = 0; j < 16; j++) a = fmaf(sFc[o * 16 + j], attn[j], a);
        out[v * 2 + o] = a;
    }
}

// ============================================================================
extern "C" void kernel_launch(void* const* d_in, const int* in_sizes, int n_in,
                              void* d_out, int out_size) {
    const float* prices = (const float*)d_in[0];
    const float* node   = (const float*)d_in[1];
    const int*   he_mem = (const int*)d_in[2];
    const int*   ve     = (const int*)d_in[3];
    const float* Wih_p  = (const float*)d_in[4];
    const float* Whh_p  = (const float*)d_in[5];
    const float* bih_p  = (const float*)d_in[6];
    const float* bhh_p  = (const float*)d_in[7];
    const float* Wih_m  = (const float*)d_in[8];
    const float* Whh_m  = (const float*)d_in[9];
    const float* bih_m  = (const float*)d_in[10];
    const float* bhh_m  = (const float*)d_in[11];
    const float* tw     = (const float*)d_in[12];
    const float* tb     = (const float*)d_in[13];
    const float* cw     = (const float*)d_in[14];
    const float* cbv    = (const float*)d_in[15];
    const float* w1     = (const float*)d_in[16];
    const float* b1     = (const float*)d_in[17];
    const float* w2     = (const float*)d_in[18];
    const float* b2     = (const float*)d_in[19];
    const float* ain    = (const float*)d_in[20];
    const float* aout   = (const float*)d_in[21];
    const float* fcw    = (const float*)d_in[22];
    const float* fcb    = (const float*)d_in[23];
    float* out = (float*)d_out;
    (void)in_sizes; (void)n_in; (void)out_size;

    const int smem_vc = 176192;
    const int smem_ge = 41504;
    cudaFuncSetAttribute(k_vertex_conv, cudaFuncAttributeMaxDynamicSharedMemorySize, smem_vc);
    cudaFuncSetAttribute(k_he_gemm, cudaFuncAttributeMaxDynamicSharedMemorySize, smem_ge);

    k_prep_bias<<<1, 64>>>(bih_m, bhh_m);
    k_price_lstm<<<32, 128>>>(prices, Wih_p, Whh_p, bih_p, bhh_p);
    k_vertex_conv<<<TT * EE / 16, 512, smem_vc>>>(he_mem, tw, tb, cw, cbv);
    k_he_gemm<<<NROWS / 128, 512, smem_ge>>>(node, w1, Wih_m, b1, w2, b2);
    k_gather_gates<<<TT * VV / 8, 256>>>(ve);
    k_final<<<32, 128>>>(Whh_m, ain, aout, fcw, fcb, out);
}

// round 8
// speedup vs baseline: 1.2060x; 1.0719x over previous
#include <cuda_runtime.h>
#include <math.h>
#include <stdint.h>

#define TT 4
#define VV 4096
#define EE 4096
#define KK 32
#define DD 8
#define HH 16
#define BERTD 768
#define CATD 784
#define M1 196
#define NROWS (TT * EE)
#define WST 340      // words per kk row of W tile (main 0..315, tail 320..335; no overhang)

typedef unsigned long long ull;

// ---------------- scratch ----------------
__device__ __align__(256) float g_new_prices[TT * VV * HH];
__device__ __align__(256) float g_he_emb[TT * EE * HH];
__device__ __align__(256) float g_z[TT * EE];
__device__ __align__(256) float g_G[TT * EE * 64];
__device__ __align__(256) float g_gates[TT * VV * 64];
__device__ __align__(256) float g_bias[64];

__device__ __forceinline__ float sigf(float x) { return 1.0f / (1.0f + __expf(-x)); }

#define FMA2(d, a, b) asm("fma.rn.f32x2 %0, %1, %2, %0;" : "+l"(d) : "l"(a), "l"(b))
#define UNPACK2(lo, hi, p) asm("mov.b64 {%0, %1}, %2;" : "=f"(lo), "=f"(hi) : "l"(p))
#define DUP2(d, v) asm("mov.b64 %0, {%1, %1};" : "=l"(d) : "f"(v))

// ============================================================================
// K0: tiny bias precompute (also used as a profiling-slot shifter)
// ============================================================================
__global__ void k_prep_bias(const float* __restrict__ bih, const float* __restrict__ bhh) {
    int t = threadIdx.x;
    g_bias[t] = bih[t] + bhh[t];
}

// ============================================================================
// K1: price LSTM (unchanged)
// ============================================================================
__global__ void k_price_lstm(const float* __restrict__ prices,
                             const float* __restrict__ Wih, const float* __restrict__ Whh,
                             const float* __restrict__ bih, const float* __restrict__ bhh) {
    __shared__ float sWih[64], sWhh[64 * 16], sb[64];
    int tid = threadIdx.x;
    for (int i = tid; i < 64; i += 128) { sWih[i] = Wih[i]; sb[i] = bih[i] + bhh[i]; }
    for (int i = tid; i < 1024; i += 128) sWhh[i] = Whh[i];
    __syncthreads();
    int v = blockIdx.x * 128 + tid;
    float h[16], c[16];
#pragma unroll
    for (int j = 0; j < 16; j++) { h[j] = 0.f; c[j] = 0.f; }
#pragma unroll
    for (int t = 0; t < TT; t++) {
        float x = prices[t * VV + v];
        float hn[16];
#pragma unroll
        for (int j = 0; j < 16; j++) {
            float gi = fmaf(sWih[j],      x, sb[j]);
            float gf = fmaf(sWih[16 + j], x, sb[16 + j]);
            float gg = fmaf(sWih[32 + j], x, sb[32 + j]);
            float go = fmaf(sWih[48 + j], x, sb[48 + j]);
#pragma unroll
            for (int u = 0; u < 16; u++) {
                float hv = h[u];
                gi = fmaf(sWhh[j * 16 + u], hv, gi);
                gf = fmaf(sWhh[(16 + j) * 16 + u], hv, gf);
                gg = fmaf(sWhh[(32 + j) * 16 + u], hv, gg);
                go = fmaf(sWhh[(48 + j) * 16 + u], hv, go);
            }
            float cn = sigf(gf) * c[j] + sigf(gi) * tanhf(gg);
            c[j] = cn;
            hn[j] = sigf(go) * tanhf(cn);
        }
#pragma unroll
        for (int j = 0; j < 16; j++) { h[j] = hn[j]; g_new_prices[(t * VV + v) * HH + j] = hn[j]; }
    }
}

// ============================================================================
// K2: VertexConv (unchanged)
// ============================================================================
__global__ void __launch_bounds__(512, 1) k_vertex_conv(
        const int* __restrict__ he_members,
        const float* __restrict__ trans_w, const float* __restrict__ trans_b,
        const float* __restrict__ conv_w, const float* __restrict__ conv_b) {
    extern __shared__ char smv[];
    ull*   w2   = (ull*)smv;                         // [8][1024]
    ull*   regA = (ull*)(smv + 65536);               // [16 warps][32][9]
    float* mlt  = (float*)(smv + 102400);            // [16 warps][32][33]
    float* aA   = (float*)(smv + 169984);            // [16 warps][33]
    float* tb_s = (float*)(smv + 172096);            // [1024]
    __shared__ float s_cw[32];
    int tid = threadIdx.x;
#pragma unroll
    for (int i = 0; i < 16; i++) {
        int idx = tid + 512 * i;
        int d2 = idx >> 10, m = idx & 1023;
        float2 v = *(const float2*)(trans_w + m * 16 + d2 * 2);
        w2[d2 * 1024 + m] = *(ull*)&v;
    }
    tb_s[tid] = trans_b[tid];
    tb_s[tid + 512] = trans_b[tid + 512];
    if (tid < 32) s_cw[tid] = conv_w[tid];
    __syncthreads();
    float cb = conv_b[0];
    int w = tid >> 5, lane = tid & 31;
    int ih = blockIdx.x * 16 + w;
    int t = ih >> 12;
    ull* regw = regA + w * 288;
    float* mw = mlt + w * 1056;
    float* aw = aA + w * 33;
    {
        int vidx = he_members[ih * KK + lane];
        const float2* src = (const float2*)(g_new_prices + (t * VV + vidx) * HH);
#pragma unroll
        for (int d2 = 0; d2 < 8; d2++) {
            float2 v = src[d2];
            regw[lane * 9 + d2] = *(ull*)&v;
        }
    }
    __syncwarp();
#pragma unroll 4
    for (int k = 0; k < 32; k++) {
        const ull* rr = regw + k * 9;
        int mcol = k * 32 + lane;
        ull acc2 = 0ull;
#pragma unroll
        for (int d2 = 0; d2 < 8; d2++) FMA2(acc2, rr[d2], w2[d2 * 1024 + mcol]);
        float lo, hi;
        UNPACK2(lo, hi, acc2);
        mw[k * 33 + lane] = lo + hi + tb_s[mcol];
    }
    __syncwarp();
    {
        float r[32];
        float* mrow = mw + lane * 33;
        float mx = -1e30f;
#pragma unroll
        for (int j = 0; j < 32; j++) { r[j] = mrow[j]; mx = fmaxf(mx, r[j]); }
        float s = 0.f;
#pragma unroll
        for (int j = 0; j < 32; j++) { r[j] = __expf(r[j] - mx); s += r[j]; }
        float f = s_cw[lane] / s;
#pragma unroll
        for (int j = 0; j < 32; j++) mrow[j] = r[j] * f;
    }
    __syncwarp();
    {
        float aj = 0.f;
#pragma unroll
        for (int k = 0; k < 32; k++) aj += mw[k * 33 + lane];
        aw[lane] = aj;
    }
    __syncwarp();
    if (lane < 16) {
        const float* regf = (const float*)regw;
        float acc = cb;
#pragma unroll
        for (int j = 0; j < 32; j++) acc = fmaf(aw[j], regf[j * 18 + lane], acc);
        g_he_emb[ih * HH + lane] = acc;
    }
}

// ============================================================================
// K3 v5: FFMA2 GEMM with ROW-PAIR packing.
// A [kk][132] plain (adjacent rows pack naturally into ull); W [kk][340] plain
// scalars (main cols in 20-word groups, tail cols 256..259 at 320+cg),
// duplicated in REGISTERS via mov.b64 (ALU pipe is idle).
// 256 threads: cg=tid&15 (17 cols), rg=tid>>4 (8 rows = 4 row-pairs).
// Per-warp LDS/kk ~1.2KB for 68 FMA2 -> FMA2-throughput-bound (~112us floor).
// Shared: wd 21760 | a_s @21760 (8448) | sb1 @30208 | sw2 @30992 |
//   zred @31776 (8704) -> 40480 total
// ============================================================================
__global__ void __launch_bounds__(256, 1) k_he_gemm(
        const float* __restrict__ node_embs,
        const float* __restrict__ W1, const float* __restrict__ Wm,
        const float* __restrict__ b1, const float* __restrict__ w2,
        const float* __restrict__ b2v) {
    extern __shared__ char smg[];
    float* wd   = (float*)smg;               // [16][340]
    float* a_s  = (float*)(smg + 21760);     // [16][132]
    float* sb1  = (float*)(smg + 30208);     // [196]
    float* sw2  = (float*)(smg + 30992);     // [196]
    float* zred = (float*)(smg + 31776);     // [128][17]

    int tid = threadIdx.x;
    int cg = tid & 15, rg = tid >> 4;
    int row0 = blockIdx.x * 128;

    if (tid < M1) { sb1[tid] = b1[tid]; sw2[tid] = w2[tid]; }

    // ---- W staging: 5 float4 slots covering 272 rows x 4 float4 of the panel
    const float4* wsrc[5]; uint32_t wbase[5]; int wmode[5];
#pragma unroll
    for (int i = 0; i < 5; i++) {
        int idx4 = tid + 256 * i;            // 0..1279; real data < 1040
        int m = idx4 >> 2, q = idx4 & 3;
        wmode[i] = (idx4 < 1040) ? 1 : 0;    // m<260 real; cols>=260 are never read usefully
        const float* s = (m < M1) ? (W1 + (size_t)m * CATD) : (Wm + (size_t)(m - M1) * CATD);
        wsrc[i] = (const float4*)s + q;      // chunk 0: cols q*4..q*4+3
        if (m < 256) wbase[i] = (uint32_t)((q * 4) * WST + (m >> 4) * 20 + (m & 15));
        else         wbase[i] = (uint32_t)((q * 4) * WST + 320 + (m - 256));
    }
    // ---- A staging: 2 float4 slots covering 128 rows x 4 float4
    const float4* asrc[2]; uint32_t abase[2];
#pragma unroll
    for (int i = 0; i < 2; i++) {
        int idx4 = tid + 256 * i;            // 0..511
        int r = idx4 >> 2, q = idx4 & 3;
        abase[i] = (uint32_t)((q * 4) * 132 + r);
        asrc[i] = (const float4*)(node_embs + (size_t)(row0 + r) * BERTD) + q;  // for chunks >= 1
    }

    // prefetch chunk 0
    float4 wpre[5], apre[2];
#pragma unroll
    for (int i = 0; i < 5; i++) {
        wpre[i] = make_float4(0.f, 0.f, 0.f, 0.f);
        if (wmode[i]) wpre[i] = *wsrc[i];
    }
#pragma unroll
    for (int i = 0; i < 2; i++) {
        int idx4 = tid + 256 * i;
        int r = idx4 >> 2, q = idx4 & 3;
        apre[i] = *((const float4*)(g_he_emb + (size_t)(row0 + r) * HH) + q);
    }

    ull acc[4][16], acct[4];
#pragma unroll
    for (int p = 0; p < 4; p++) {
        acct[p] = 0ull;
#pragma unroll
        for (int j = 0; j < 16; j++) acc[p][j] = 0ull;
    }

    for (int ch = 0; ch < 49; ch++) {
        // commit staged regs (scalar STS; tail region race-free by construction)
#pragma unroll
        for (int i = 0; i < 5; i++) {
            if (wmode[i]) {
                wd[wbase[i]]           = wpre[i].x;
                wd[wbase[i] + WST]     = wpre[i].y;
                wd[wbase[i] + 2 * WST] = wpre[i].z;
                wd[wbase[i] + 3 * WST] = wpre[i].w;
            }
        }
#pragma unroll
        for (int i = 0; i < 2; i++) {
            a_s[abase[i]]       = apre[i].x;
            a_s[abase[i] + 132] = apre[i].y;
            a_s[abase[i] + 264] = apre[i].z;
            a_s[abase[i] + 396] = apre[i].w;
        }
        __syncthreads();
        // prefetch next chunk
        if (ch < 48) {
#pragma unroll
            for (int i = 0; i < 5; i++) {
                if (wmode[i]) { wpre[i] = wsrc[i][4]; wsrc[i] += 4; }
            }
            if (ch == 0) {
#pragma unroll
                for (int i = 0; i < 2; i++) apre[i] = asrc[i][0];
            } else {
#pragma unroll
                for (int i = 0; i < 2; i++) { apre[i] = asrc[i][4]; asrc[i] += 4; }
            }
        }
        // compute chunk
#pragma unroll 4
        for (int kk = 0; kk < 16; kk++) {
            const float* ab = a_s + kk * 132 + rg * 8;
            ulonglong2 au0 = *(const ulonglong2*)ab;
            ulonglong2 au1 = *(const ulonglong2*)(ab + 4);
            ull ap0 = au0.x, ap1 = au0.y, ap2 = au1.x, ap3 = au1.y;
            const float4* wrow = (const float4*)(wd + kk * WST + cg * 20);
            float4 wa = wrow[0], wb = wrow[1], wc = wrow[2], we = wrow[3];
#define COLFMA(J, WV) { ull wdp_; DUP2(wdp_, WV); \
            FMA2(acc[0][J], ap0, wdp_); FMA2(acc[1][J], ap1, wdp_); \
            FMA2(acc[2][J], ap2, wdp_); FMA2(acc[3][J], ap3, wdp_); }
            COLFMA(0,  wa.x) COLFMA(1,  wa.y) COLFMA(2,  wa.z) COLFMA(3,  wa.w)
            COLFMA(4,  wb.x) COLFMA(5,  wb.y) COLFMA(6,  wb.z) COLFMA(7,  wb.w)
            COLFMA(8,  wc.x) COLFMA(9,  wc.y) COLFMA(10, wc.z) COLFMA(11, wc.w)
            COLFMA(12, we.x) COLFMA(13, we.y) COLFMA(14, we.z) COLFMA(15, we.w)
#undef COLFMA
            float wtl = wd[kk * WST + 320 + cg];
            ull wdt; DUP2(wdt, wtl);
            FMA2(acct[0], ap0, wdt); FMA2(acct[1], ap1, wdt);
            FMA2(acct[2], ap2, wdt); FMA2(acct[3], ap3, wdt);
        }
        __syncthreads();
    }

    // epilogue: acc[p][j] = (rows rg*8+2p, rg*8+2p+1) x col cg*16+j
    float zp[8];
#pragma unroll
    for (int rr = 0; rr < 8; rr++) zp[rr] = 0.f;
#pragma unroll
    for (int p = 0; p < 4; p++) {
#pragma unroll
        for (int j = 0; j < 16; j++) {
            int c = cg * 16 + j;
            float lo, hi;
            UNPACK2(lo, hi, acc[p][j]);
            if (c < M1) {
                zp[2 * p]     = fmaf(sw2[c], fmaxf(lo + sb1[c], 0.f), zp[2 * p]);
                zp[2 * p + 1] = fmaf(sw2[c], fmaxf(hi + sb1[c], 0.f), zp[2 * p + 1]);
            } else if (c < 260) {
                int r = row0 + rg * 8 + 2 * p;
                g_G[(size_t)r * 64 + (c - M1)]       = lo;
                g_G[(size_t)(r + 1) * 64 + (c - M1)] = hi;
            }
        }
        {
            int c = 256 + cg;
            if (c < 260) {
                float lo, hi;
                UNPACK2(lo, hi, acct[p]);
                int r = row0 + rg * 8 + 2 * p;
                g_G[(size_t)r * 64 + (c - M1)]       = lo;
                g_G[(size_t)(r + 1) * 64 + (c - M1)] = hi;
            }
        }
    }
#pragma unroll
    for (int rr = 0; rr < 8; rr++) zred[(rg * 8 + rr) * 17 + cg] = zp[rr];
    __syncthreads();
    if (tid < 128) {
        float s = b2v[0];
#pragma unroll
        for (int c = 0; c < 16; c++) s += zred[tid * 17 + c];
        g_z[row0 + tid] = s;
    }
}

// ============================================================================
// K4: per-vertex softmax over 8 edges + weighted sum of G rows -> gates.
// ============================================================================
__global__ void __launch_bounds__(256) k_gather_gates(const int* __restrict__ ve) {
    __shared__ float sbias[64];
    int tid = threadIdx.x;
    if (tid < 64) sbias[tid] = g_bias[tid];
    __syncthreads();
    int w = tid >> 5, lane = tid & 31;
    int tv = blockIdx.x * 8 + w;
    int t = tv >> 12;
    int eld = 0;
    if (lane < 8) eld = ve[tv * DD + lane];
    float zld = (lane < 8) ? g_z[t * EE + eld] : 0.f;
    float zv[8]; int ev[8];
#pragma unroll
    for (int d = 0; d < 8; d++) {
        zv[d] = __shfl_sync(0xffffffffu, zld, d);
        ev[d] = __shfl_sync(0xffffffffu, eld, d);
    }
    float mx = zv[0];
#pragma unroll
    for (int d = 1; d < 8; d++) mx = fmaxf(mx, zv[d]);
    float s = 0.f;
#pragma unroll
    for (int d = 0; d < 8; d++) { zv[d] = __expf(zv[d] - mx); s += zv[d]; }
    float inv = 1.f / s;
    float a0 = 0.f, a1 = 0.f;
#pragma unroll
    for (int d = 0; d < 8; d++) {
        const float* gr = g_G + (size_t)(t * EE + ev[d]) * 64;
        float wv = zv[d] * inv;
        a0 = fmaf(wv, gr[lane], a0);
        a1 = fmaf(wv, gr[lane + 32], a1);
    }
    g_gates[(size_t)tv * 64 + lane]      = a0 + sbias[lane];
    g_gates[(size_t)tv * 64 + lane + 32] = a1 + sbias[lane + 32];
}

// ============================================================================
// K5: second LSTM + residual + attention + FC (unchanged)
// ============================================================================
__global__ void k_final(const float* __restrict__ Whh,
                        const float* __restrict__ attn_in, const float* __restrict__ attn_out,
                        const float* __restrict__ fc_w, const float* __restrict__ fc_b,
                        float* __restrict__ out) {
    __shared__ float sWhh[1024], sAin[256], sAout[512], sFc[32], sFcb[2];
    int tid = threadIdx.x;
    for (int i = tid; i < 1024; i += 128) sWhh[i] = Whh[i];
    for (int i = tid; i < 256; i += 128) sAin[i] = attn_in[i];
    for (int i = tid; i < 512; i += 128) sAout[i] = attn_out[i];
    if (tid < 32) sFc[tid] = fc_w[tid];
    if (tid < 2) sFcb[tid] = fc_b[tid];
    __syncthreads();
    int v = blockIdx.x * 128 + tid;
    float h[16], c[16], la[4][16];
#pragma unroll
    for (int j = 0; j < 16; j++) { h[j] = 0.f; c[j] = 0.f; }
#pragma unroll
    for (int t = 0; t < 4; t++) {
        float gin[64];
        const float4* gp = (const float4*)(g_gates + (size_t)(t * VV + v) * 64);
#pragma unroll
        for (int i = 0; i < 16; i++) {
            float4 x = gp[i];
            gin[4 * i] = x.x; gin[4 * i + 1] = x.y; gin[4 * i + 2] = x.z; gin[4 * i + 3] = x.w;
        }
        float hn[16];
#pragma unroll
        for (int j = 0; j < 16; j++) {
            float gi = gin[j], gf = gin[16 + j], gg = gin[32 + j], go = gin[48 + j];
#pragma unroll
            for (int u = 0; u < 16; u++) {
                float hv = h[u];
                gi = fmaf(sWhh[j * 16 + u], hv, gi);
                gf = fmaf(sWhh[(16 + j) * 16 + u], hv, gf);
                gg = fmaf(sWhh[(32 + j) * 16 + u], hv, gg);
                go = fmaf(sWhh[(48 + j) * 16 + u], hv, go);
            }
            float cn = sigf(gf) * c[j] + sigf(gi) * tanhf(gg);
            c[j] = cn;
            hn[j] = sigf(go) * tanhf(cn);
        }
#pragma unroll
        for (int j = 0; j < 16; j++) {
            h[j] = hn[j];
            la[t][j] = hn[j] + g_new_prices[(t * VV + v) * HH + j];
        }
    }
    float q[16];
#pragma unroll
    for (int j = 0; j < 16; j++) {
        float a = 0.f;
#pragma unroll
        for (int u = 0; u < 16; u++) a = fmaf(sAin[j * 16 + u], la[3][u], a);
        q[j] = a;
    }
    float sc[4], mx = -1e30f;
#pragma unroll
    for (int t = 0; t < 4; t++) {
        float a = 0.f;
#pragma unroll
        for (int j = 0; j < 16; j++) a = fmaf(q[j], la[t][j], a);
        sc[t] = a;
        mx = fmaxf(mx, a);
    }
    float ssum = 0.f;
#pragma unroll
    for (int t = 0; t < 4; t++) { sc[t] = __expf(sc[t] - mx); ssum += sc[t]; }
    float inv = 1.f / ssum;
    float mixv[16];
#pragma unroll
    for (int j = 0; j < 16; j++) {
        float m = 0.f;
#pragma unroll
        for (int t = 0; t < 4; t++) m = fmaf(sc[t] * inv, la[t][j], m);
        mixv[j] = m;
    }
    float attn[16];
#pragma unroll
    for (int j = 0; j < 16; j++) {
        float a = 0.f;
#pragma unroll
        for (int u = 0; u < 16; u++) a = fmaf(sAout[j * 32 + u], mixv[u], a);
#pragma unroll
        for (int u = 0; u < 16; u++) a = fmaf(sAout[j * 32 + 16 + u], q[u], a);
        attn[j] = tanhf(a);
    }
#pragma unroll
    for (int o = 0; o < 2; o++) {
        float a = sFcb[o];
#pragma unroll
        for (int j = 0; j < 16; j++) a = fmaf(sFc[o * 16 + j], attn[j], a);
        out[v * 2 + o] = a;
    }
}

// ============================================================================
extern "C" void kernel_launch(void* const* d_in, const int* in_sizes, int n_in,
                              void* d_out, int out_size) {
    const float* prices = (const float*)d_in[0];
    const float* node   = (const float*)d_in[1];
    const int*   he_mem = (const int*)d_in[2];
    const int*   ve     = (const int*)d_in[3];
    const float* Wih_p  = (const float*)d_in[4];
    const float* Whh_p  = (const float*)d_in[5];
    const float* bih_p  = (const float*)d_in[6];
    const float* bhh_p  = (const float*)d_in[7];
    const float* Wih_m  = (const float*)d_in[8];
    const float* Whh_m  = (const float*)d_in[9];
    const float* bih_m  = (const float*)d_in[10];
    const float* bhh_m  = (const float*)d_in[11];
    const float* tw     = (const float*)d_in[12];
    const float* tb     = (const float*)d_in[13];
    const float* cw     = (const float*)d_in[14];
    const float* cbv    = (const float*)d_in[15];
    const float* w1     = (const float*)d_in[16];
    const float* b1     = (const float*)d_in[17];
    const float* w2     = (const float*)d_in[18];
    const float* b2     = (const float*)d_in[19];
    const float* ain    = (const float*)d_in[20];
    const float* aout   = (const float*)d_in[21];
    const float* fcw    = (const float*)d_in[22];
    const float* fcb    = (const float*)d_in[23];
    float* out = (float*)d_out;
    (void)in_sizes; (void)n_in; (void)out_size;

    const int smem_vc = 176192;
    const int smem_ge = 40480;
    cudaFuncSetAttribute(k_vertex_conv, cudaFuncAttributeMaxDynamicSharedMemorySize, smem_vc);
    cudaFuncSetAttribute(k_he_gemm, cudaFuncAttributeMaxDynamicSharedMemorySize, smem_ge);

    k_prep_bias<<<1, 64>>>(bih_m, bhh_m);                                   // 0
    k_price_lstm<<<32, 128>>>(prices, Wih_p, Whh_p, bih_p, bhh_p);          // 1
    k_prep_bias<<<1, 64>>>(bih_m, bhh_m);                                   // 2 (slot shifter)
    k_vertex_conv<<<TT * EE / 16, 512, smem_vc>>>(he_mem, tw, tb, cw, cbv); // 3 <- profiled
    k_he_gemm<<<NROWS / 128, 256, smem_ge>>>(node, w1, Wih_m, b1, w2, b2);  // 4
    k_gather_gates<<<TT * VV / 8, 256>>>(ve);                               // 5
    k_final<<<32, 128>>>(Whh_m, ain, aout, fcw, fcb, out);                  // 6
}